// round 1
// baseline (speedup 1.0000x reference)
#include <cuda_runtime.h>

#define B_ 64
#define S_ 1024
#define D_ 64
#define L_ 512
#define O_ 10

// Scratch (allocation-free rule: __device__ globals)
__device__ float g_vL[B_][D_];
__device__ float g_wR[B_][D_];
__device__ float g_WrT[L_ * D_ * D_ * 2];  // transposed + site-reversed W_right

// WrT[u][r][l][i] = W_right[(L-1)-u][l][r][i]
__global__ void transpose_wr_kernel(const float* __restrict__ Wr) {
    int u = blockIdx.x;                  // reversed site index
    int t = (L_ - 1) - u;
    const float2* src = (const float2*)(Wr) + t * (D_ * D_);
    float2* dst = (float2*)(g_WrT) + u * (D_ * D_);
    __shared__ float2 tile[D_ * (D_ + 1)];
    for (int idx = threadIdx.x; idx < D_ * D_; idx += blockDim.x) {
        int l = idx >> 6, r = idx & 63;
        tile[r * (D_ + 1) + l] = src[idx];
    }
    __syncthreads();
    for (int idx = threadIdx.x; idx < D_ * D_; idx += blockDim.x) {
        int rr = idx >> 6, ll = idx & 63;
        dst[idx] = tile[rr * (D_ + 1) + ll];
    }
}

// One block per (batch, side). 256 threads = 64 outputs (r) x 4 l-quarters (q).
// Per step: v'[r] = sum_l v[l] * (W0[l][r]*x0 + W1[l][r]*x1)
// Left: W layout [s][l][r][i] direct. Right: uses g_WrT so identical pattern.
__global__ void __launch_bounds__(256, 1)
chain_kernel(const float* __restrict__ x, const float* __restrict__ Wl) {
    int b = blockIdx.x;
    int side = blockIdx.y;               // 0 = left, 1 = right
    const float* W = side ? (const float*)g_WrT : Wl;
    int tid = threadIdx.x;
    int r = tid & 63;
    int q = tid >> 6;                    // 0..3, l in [16q, 16q+16)

    __shared__ float vbuf[2][D_];
    __shared__ float part[4][D_];
    __shared__ float2 xsh[L_];

    // Stage this (b, side)'s x features: left sites [0,512), right sites [512,1024)
    const float2* xsrc = (const float2*)(x) + b * S_ + side * L_;
    for (int i = tid; i < L_; i += 256) xsh[i] = xsrc[i];
    if (tid < 64) vbuf[0][tid] = (tid == 0) ? 1.0f : 0.0f;
    __syncthreads();

    // Thread's W elements: (s, l=q*16+j, r), stored as float2 (i=0,1 contiguous)
    const float2* wp = (const float2*)W + (q * 16) * D_ + r;
    float2 wreg[2][16];
    #pragma unroll
    for (int j = 0; j < 16; j++) wreg[0][j] = wp[j * D_];
    wp += D_ * D_;

    int cur = 0;
    #pragma unroll 2
    for (int s = 0; s < L_; s++) {
        int pb = s & 1;
        // Prefetch next site's W into the other register buffer (hides L2 latency)
        if (s < L_ - 1) {
            #pragma unroll
            for (int j = 0; j < 16; j++) wreg[pb ^ 1][j] = wp[j * D_];
            wp += D_ * D_;
        }
        float2 xs = xsh[side ? (L_ - 1 - s) : s];   // right chain scans reversed
        const float* v = vbuf[cur];
        float acc0 = 0.f, acc1 = 0.f;
        #pragma unroll
        for (int j = 0; j < 16; j += 2) {
            float m0 = wreg[pb][j].x * xs.x + wreg[pb][j].y * xs.y;
            float m1 = wreg[pb][j + 1].x * xs.x + wreg[pb][j + 1].y * xs.y;
            acc0 += v[q * 16 + j] * m0;
            acc1 += v[q * 16 + j + 1] * m1;
        }
        part[q][r] = acc0 + acc1;
        __syncthreads();
        if (q == 0)
            vbuf[cur ^ 1][r] = (part[0][r] + part[1][r]) + (part[2][r] + part[3][r]);
        cur ^= 1;
        __syncthreads();
    }
    if (tid < 64) {
        if (side) g_wR[b][tid] = vbuf[cur][tid];
        else      g_vL[b][tid] = vbuf[cur][tid];
    }
}

// out[b][o] = sum_l vL[l] * sum_r core[o][l][r] * wR[r]
__global__ void output_kernel(const float* __restrict__ core, float* __restrict__ out) {
    int b = blockIdx.x;
    int l = threadIdx.x;                 // 64 threads
    __shared__ float wsh[D_];
    __shared__ float red[D_];
    wsh[l] = g_wR[b][l];
    float vl = g_vL[b][l];
    __syncthreads();
    for (int o = 0; o < O_; o++) {
        const float* c = core + (o * D_ + l) * D_;
        float s0 = 0.f, s1 = 0.f;
        #pragma unroll 8
        for (int rr = 0; rr < D_; rr += 2) {
            s0 += c[rr] * wsh[rr];
            s1 += c[rr + 1] * wsh[rr + 1];
        }
        red[l] = vl * (s0 + s1);
        __syncthreads();
        for (int off = 32; off > 0; off >>= 1) {
            if (l < off) red[l] += red[l + off];
            __syncthreads();
        }
        if (l == 0) out[b * O_ + o] = red[0];
        __syncthreads();
    }
}

extern "C" void kernel_launch(void* const* d_in, const int* in_sizes, int n_in,
                              void* d_out, int out_size) {
    const float* x    = (const float*)d_in[0];   // [64, 1024, 2]
    const float* Wl   = (const float*)d_in[1];   // [512, 64, 64, 2]
    const float* core = (const float*)d_in[2];   // [10, 64, 64]
    const float* Wr   = (const float*)d_in[3];   // [512, 64, 64, 2]
    float* out = (float*)d_out;                  // [64, 10]

    transpose_wr_kernel<<<L_, 256>>>(Wr);
    dim3 grid(B_, 2);
    chain_kernel<<<grid, 256>>>(x, Wl);
    output_kernel<<<B_, 64>>>(core, out);
}